// round 4
// baseline (speedup 1.0000x reference)
#include <cuda_runtime.h>
#include <cuda_bf16.h>

#define BB 8
#define CC 128
#define LL 4096
#define PP 96
#define DD 16

#define TQ 64
#define TM 128
#define SSTR 132
#define QSTR 68

// -------- scratch (static device allocations only) --------
__device__ float  g_hraw[BB*CC*LL];   // pre-BN conv output [B][C][L]
__device__ float  g_q[BB*LL*DD];      // [B][L][16]
__device__ float  g_k[BB*DD*LL];      // [B][16][L]
__device__ float  g_u[BB*LL*PP];      // [B][L][96]
__device__ double g_csum[CC];
__device__ double g_csumsq[CC];
__device__ float  g_scale[CC];
__device__ float  g_shift[CC];
__device__ float  g_Wpv[PP*CC];
__device__ float  g_bpv[PP];

// -------- packed f32x2 helpers (Blackwell FFMA2 path) --------
__device__ __forceinline__ unsigned long long pk2(float lo, float hi) {
    unsigned long long r;
    asm("mov.b64 %0, {%1, %2};" : "=l"(r) : "f"(lo), "f"(hi));
    return r;
}
__device__ __forceinline__ void upk2(unsigned long long v, float& lo, float& hi) {
    asm("mov.b64 {%0, %1}, %2;" : "=f"(lo), "=f"(hi) : "l"(v));
}
__device__ __forceinline__ unsigned long long ffma2(unsigned long long a,
                                                    unsigned long long b,
                                                    unsigned long long c) {
    unsigned long long d;
    asm("fma.rn.f32x2 %0, %1, %2, %3;" : "=l"(d) : "l"(a), "l"(b), "l"(c));
    return d;
}
__device__ __forceinline__ unsigned long long fmul2(unsigned long long a,
                                                    unsigned long long b) {
    unsigned long long d;
    asm("mul.rn.f32x2 %0, %1, %2;" : "=l"(d) : "l"(a), "l"(b));
    return d;
}

// -------- K0: zero BN stat accumulators (graph replays reuse them) --------
__global__ void k0_zero() {
    int t = threadIdx.x;
    if (t < CC) { g_csum[t] = 0.0; g_csumsq[t] = 0.0; }
}

// -------- Kwpv: Wpv = W2 @ Wv  [96,128], bpv = W2 @ bv --------
__global__ void k_wpv(const float* __restrict__ W2, const float* __restrict__ Wv,
                      const float* __restrict__ bv) {
    __shared__ float w2s[CC];
    int p = blockIdx.x, c = threadIdx.x;
    w2s[c] = W2[p * CC + c];
    __syncthreads();
    float acc = 0.f;
#pragma unroll 4
    for (int i = 0; i < CC; i++) acc = fmaf(w2s[i], Wv[i * CC + c], acc);
    g_Wpv[p * CC + c] = acc;
    if (c == 0) {
        float a = 0.f;
        for (int i = 0; i < CC; i++) a = fmaf(w2s[i], bv[i], a);
        g_bpv[p] = a;
    }
}

// -------- K1: ConvTranspose (outer product x * Wt) + per-channel stats --------
// h[b,o,l] = sum_i x[b,i] * Wt[i,o,l] + bt[o]
__global__ __launch_bounds__(256) void k1_conv(const float* __restrict__ x,
                                               const float* __restrict__ Wt,
                                               const float* __restrict__ bt) {
    __shared__ float xs[BB * CC];
    __shared__ float red[16];
    int t = threadIdx.x;
    for (int i = t; i < BB * CC; i += 256) xs[i] = x[i];
    __syncthreads();
    int o = blockIdx.x;
    int l = (blockIdx.y << 8) + t;
    const float* wp = Wt + (size_t)o * LL + l;
    float acc[BB];
#pragma unroll
    for (int b = 0; b < BB; b++) acc[b] = 0.f;
#pragma unroll 4
    for (int i = 0; i < CC; i++) {
        float w = wp[(size_t)i * (CC * LL)];
#pragma unroll
        for (int b = 0; b < BB; b++) acc[b] = fmaf(xs[b * CC + i], w, acc[b]);
    }
    float bo = bt[o];
    float s1 = 0.f, s2 = 0.f;
#pragma unroll
    for (int b = 0; b < BB; b++) {
        float v = acc[b] + bo;
        g_hraw[((b * CC + o) << 12) + l] = v;
        s1 += v;
        s2 = fmaf(v, v, s2);
    }
#pragma unroll
    for (int off = 16; off; off >>= 1) {
        s1 += __shfl_xor_sync(0xffffffffu, s1, off);
        s2 += __shfl_xor_sync(0xffffffffu, s2, off);
    }
    int w = t >> 5, lane = t & 31;
    if (lane == 0) { red[w] = s1; red[8 + w] = s2; }
    __syncthreads();
    if (t == 0) {
        float a = 0.f, b2s = 0.f;
#pragma unroll
        for (int i = 0; i < 8; i++) { a += red[i]; b2s += red[8 + i]; }
        atomicAdd(&g_csum[o], (double)a);
        atomicAdd(&g_csumsq[o], (double)b2s);
    }
}

// -------- K2: fold BN into per-channel scale/shift --------
__global__ void k2_bn(const float* __restrict__ gamma, const float* __restrict__ beta) {
    int c = threadIdx.x;
    if (c < CC) {
        double n = (double)(BB * LL);
        double m = g_csum[c] / n;
        double v = g_csumsq[c] / n - m * m;
        float sc = gamma[c] * rsqrtf((float)v + 1e-5f);
        g_scale[c] = sc;
        g_shift[c] = beta[c] - (float)m * sc;
    }
}

// -------- K3: fused BN+ReLU + {q,k,u} projections --------
// combined row space: rows 0..15 = Wq, 16..31 = Wk, 32..127 = Wpv
__global__ __launch_bounds__(256) void k3_proj(const float* __restrict__ Wq,
                                               const float* __restrict__ bq,
                                               const float* __restrict__ Wk,
                                               const float* __restrict__ bk) {
    __shared__ float hn[CC * 64];
    int t = threadIdx.x;
    int b = blockIdx.y;
    int l0 = blockIdx.x * 64;
    for (int idx = t; idx < CC * 64; idx += 256) {
        int c = idx >> 6, j = idx & 63;
        float v = g_hraw[((b * CC + c) << 12) + l0 + j];
        v = fmaf(v, g_scale[c], g_shift[c]);
        hn[idx] = fmaxf(v, 0.f);
    }
    __syncthreads();
    int jg = t & 15, rg = t >> 4;
    int j0 = jg << 2, r0 = rg << 3;
    const float* Wbase;
    if (r0 < 16)      Wbase = Wq + r0 * CC;
    else if (r0 < 32) Wbase = Wk + (r0 - 16) * CC;
    else              Wbase = g_Wpv + (r0 - 32) * CC;
    float acc[8][4];
#pragma unroll
    for (int r = 0; r < 8; r++)
#pragma unroll
        for (int j = 0; j < 4; j++) acc[r][j] = 0.f;
#pragma unroll 2
    for (int c = 0; c < CC; c++) {
        float4 h4 = *reinterpret_cast<const float4*>(&hn[(c << 6) + j0]);
#pragma unroll
        for (int r = 0; r < 8; r++) {
            float w = __ldg(&Wbase[r * CC + c]);
            acc[r][0] = fmaf(w, h4.x, acc[r][0]);
            acc[r][1] = fmaf(w, h4.y, acc[r][1]);
            acc[r][2] = fmaf(w, h4.z, acc[r][2]);
            acc[r][3] = fmaf(w, h4.w, acc[r][3]);
        }
    }
    if (r0 < 16) {
#pragma unroll
        for (int r = 0; r < 8; r++) {
            float bias = bq[r0 + r];
#pragma unroll
            for (int j = 0; j < 4; j++)
                g_q[(((b << 12) + l0 + j0 + j) << 4) + r0 + r] = acc[r][j] + bias;
        }
    } else if (r0 < 32) {
#pragma unroll
        for (int r = 0; r < 8; r++) {
            float bias = bk[r0 - 16 + r];
#pragma unroll
            for (int j = 0; j < 4; j++)
                g_k[((b * DD + r0 - 16 + r) << 12) + l0 + j0 + j] = acc[r][j] + bias;
        }
    } else {
#pragma unroll
        for (int r = 0; r < 8; r++) {
            float bias = g_bpv[r0 - 32 + r];
#pragma unroll
            for (int j = 0; j < 4; j++)
                g_u[(((b << 12) + l0 + j0 + j) * PP) + r0 - 32 + r] = acc[r][j] + bias;
        }
    }
}

// -------- K4: flash attention with folded output projection --------
// per block: batch b, 64 queries. Online softmax over 32 key-tiles of 128.
// y[b,p,l] = (sum_m e^{s_lm - max} u[p,m]) / (sum_m e^{s_lm - max}) + b2[p]
__global__ __launch_bounds__(256, 2) void k4_attn(const float* __restrict__ b2,
                                                  float* __restrict__ y) {
    extern __shared__ float sm[];
    float* k_s  = sm;                        // [16][128]
    float* u_s  = k_s + 16 * TM;             // [128][96]
    float* s_s  = u_s + TM * PP;             // [64][SSTR]
    float* q_s  = s_s + TQ * SSTR;           // [16][QSTR]
    float* rmax = q_s + 16 * QSTR;           // [64]
    float* rsum = rmax + TQ;                 // [64]
    float* resc = rsum + TQ;                 // [64]

    int b = blockIdx.y;
    int l0 = blockIdx.x * TQ;
    int t = threadIdx.x;

    // stage q tile: global [B][L][16] -> smem [d][q]
    for (int idx = t; idx < TQ * DD; idx += 256) {
        int q = idx >> 4, d = idx & 15;
        q_s[d * QSTR + q] = g_q[(((b << 12) + l0 + q) << 4) + d];
    }
    if (t < TQ) { rmax[t] = -1e30f; rsum[t] = 0.f; }

    // PV mapping: thread -> (query qi, p-quarter sub)
    int qi = t >> 2, sub = t & 3;
    unsigned long long acc2[12];
#pragma unroll
    for (int i = 0; i < 12; i++) acc2[i] = 0ull;

    // score mapping: thread -> (4 queries q0.., 8 keys m0..)
    int mg = t & 15, qg = t >> 4;
    int m0 = mg << 3, q0 = qg << 2;

    for (int mt = 0; mt < LL; mt += TM) {
        __syncthreads();  // prior PV done with u_s / s_s
        // stage k tile: [B][16][L] -> [d][m]
        for (int idx = t; idx < DD * TM; idx += 256) {
            int d = idx >> 7, m = idx & 127;
            k_s[d * TM + m] = g_k[((b * DD + d) << 12) + mt + m];
        }
        // stage u tile: [B][L][96] -> [m][p]
        for (int idx = t; idx < TM * PP; idx += 256) {
            int m = idx / PP, p = idx - m * PP;
            u_s[m * PP + p] = g_u[(((b << 12) + mt + m) * PP) + p];
        }
        __syncthreads();

        // ---- scores: S[4q][8m] via packed f32x2 FMA ----
        unsigned long long sa[16];
#pragma unroll
        for (int i = 0; i < 16; i++) sa[i] = 0ull;
#pragma unroll
        for (int d = 0; d < DD; d++) {
            float4 q4 = *reinterpret_cast<const float4*>(&q_s[d * QSTR + q0]);
            ulonglong2 ka = *reinterpret_cast<const ulonglong2*>(&k_s[d * TM + m0]);
            ulonglong2 kb = *reinterpret_cast<const ulonglong2*>(&k_s[d * TM + m0 + 4]);
            unsigned long long kp0 = ka.x, kp1 = ka.y, kp2 = kb.x, kp3 = kb.y;
            float qv[4] = {q4.x, q4.y, q4.z, q4.w};
#pragma unroll
            for (int i = 0; i < 4; i++) {
                unsigned long long qp = pk2(qv[i], qv[i]);
                sa[i * 4 + 0] = ffma2(qp, kp0, sa[i * 4 + 0]);
                sa[i * 4 + 1] = ffma2(qp, kp1, sa[i * 4 + 1]);
                sa[i * 4 + 2] = ffma2(qp, kp2, sa[i * 4 + 2]);
                sa[i * 4 + 3] = ffma2(qp, kp3, sa[i * 4 + 3]);
            }
        }
        // local row max
        float lm[4];
#pragma unroll
        for (int i = 0; i < 4; i++) {
            float mx = -1e30f;
#pragma unroll
            for (int j = 0; j < 4; j++) {
                float a, bb2;
                upk2(sa[i * 4 + j], a, bb2);
                mx = fmaxf(mx, fmaxf(a, bb2));
            }
            lm[i] = mx;
        }
        // reduce over the 16 m-group lanes (same qg half-warp)
#pragma unroll
        for (int off = 8; off; off >>= 1)
#pragma unroll
            for (int i = 0; i < 4; i++)
                lm[i] = fmaxf(lm[i], __shfl_xor_sync(0xffffffffu, lm[i], off));

        float nm[4], ps[4];
#pragma unroll
        for (int i = 0; i < 4; i++) nm[i] = fmaxf(rmax[q0 + i], lm[i]);
#pragma unroll
        for (int i = 0; i < 4; i++) {
            float a, bb2, acc = 0.f;
            float* srow = &s_s[(q0 + i) * SSTR + m0];
#pragma unroll
            for (int j = 0; j < 4; j++) {
                upk2(sa[i * 4 + j], a, bb2);
                float ea = __expf(a - nm[i]);
                float eb = __expf(bb2 - nm[i]);
                *reinterpret_cast<float2*>(srow + 2 * j) = make_float2(ea, eb);
                acc += ea + eb;
            }
            ps[i] = acc;
        }
#pragma unroll
        for (int off = 8; off; off >>= 1)
#pragma unroll
            for (int i = 0; i < 4; i++)
                ps[i] += __shfl_xor_sync(0xffffffffu, ps[i], off);
        if (mg == 0) {
#pragma unroll
            for (int i = 0; i < 4; i++) {
                int q = q0 + i;
                float om = rmax[q];
                float r = __expf(om - nm[i]);
                resc[q] = r;
                rsum[q] = rsum[q] * r + ps[i];
                rmax[q] = nm[i];
            }
        }
        __syncthreads();

        // ---- PV: acc[p] = acc[p]*rescale + sum_m e * u[p,m] ----
        {
            float r = resc[qi];
            unsigned long long rp = pk2(r, r);
#pragma unroll
            for (int i = 0; i < 12; i++) acc2[i] = fmul2(acc2[i], rp);
            const float* srow = s_s + qi * SSTR;
            const float* ub = u_s + sub * 24;
#pragma unroll 2
            for (int m = 0; m < TM; m++) {
                float s = srow[m];
                unsigned long long sp = pk2(s, s);
                const float* up = ub + m * PP;
#pragma unroll
                for (int k = 0; k < 6; k++) {
                    ulonglong2 uu = *reinterpret_cast<const ulonglong2*>(up + 4 * k);
                    acc2[2 * k]     = ffma2(sp, uu.x, acc2[2 * k]);
                    acc2[2 * k + 1] = ffma2(sp, uu.y, acc2[2 * k + 1]);
                }
            }
        }
    }

    float inv = 1.0f / rsum[qi];
#pragma unroll
    for (int k = 0; k < 12; k++) {
        float lo, hi;
        upk2(acc2[k], lo, hi);
        int p = sub * 24 + 2 * k;
        y[((b * PP + p) << 12) + l0 + qi]     = fmaf(lo, inv, b2[p]);
        y[((b * PP + p + 1) << 12) + l0 + qi] = fmaf(hi, inv, b2[p + 1]);
    }
}

extern "C" void kernel_launch(void* const* d_in, const int* in_sizes, int n_in,
                              void* d_out, int out_size) {
    const float* x     = (const float*)d_in[0];
    const float* Wt    = (const float*)d_in[1];
    const float* bt    = (const float*)d_in[2];
    const float* gamma = (const float*)d_in[3];
    const float* beta  = (const float*)d_in[4];
    const float* Wq    = (const float*)d_in[5];
    const float* bq    = (const float*)d_in[6];
    const float* Wk    = (const float*)d_in[7];
    const float* bk    = (const float*)d_in[8];
    const float* Wv    = (const float*)d_in[9];
    const float* bv    = (const float*)d_in[10];
    const float* W2    = (const float*)d_in[11];
    const float* b2    = (const float*)d_in[12];
    float* y = (float*)d_out;

    const int attn_smem = (16 * TM + TM * PP + TQ * SSTR + 16 * QSTR + 3 * TQ) * 4;
    // idempotent; also applied on the (non-captured) correctness call so the
    // attribute persists even if a during-capture call were rejected.
    cudaFuncSetAttribute(k4_attn, cudaFuncAttributeMaxDynamicSharedMemorySize, attn_smem);

    k0_zero<<<1, 128>>>();
    k_wpv<<<PP, 128>>>(W2, Wv, bv);
    k1_conv<<<dim3(CC, LL / 256), 256>>>(x, Wt, bt);
    k2_bn<<<1, 128>>>(gamma, beta);
    k3_proj<<<dim3(LL / 64, BB), 256>>>(Wq, bq, Wk, bk);
    k4_attn<<<dim3(LL / TQ, BB), 256, attn_smem>>>(b2, y);
}

// round 6
// speedup vs baseline: 2.0439x; 2.0439x over previous
#include <cuda_runtime.h>
#include <cuda_bf16.h>

#define BB 8
#define CC 128
#define LL 4096
#define PP 96
#define DD 16

#define TQ 64
#define TM 128
#define SSTR 136   // s_s row stride in floats; 136 % 32 == 8 -> conflict-friendly
#define QSTR 68

// -------- scratch (static device allocations only) --------
__device__ float  g_hraw[BB*CC*LL];   // pre-BN conv output [B][C][L]
__device__ float  g_q[BB*LL*DD];      // [B][L][16]
__device__ float  g_k[BB*DD*LL];      // [B][16][L]
__device__ float  g_u[BB*LL*PP];      // [B][L][96]
__device__ double g_csum[CC];
__device__ double g_csumsq[CC];
__device__ float  g_Wpv[PP*CC];
__device__ float  g_bpv[PP];

// -------- packed f32x2 helpers (Blackwell FFMA2 path) --------
__device__ __forceinline__ unsigned long long pk2(float lo, float hi) {
    unsigned long long r;
    asm("mov.b64 %0, {%1, %2};" : "=l"(r) : "f"(lo), "f"(hi));
    return r;
}
__device__ __forceinline__ void upk2(unsigned long long v, float& lo, float& hi) {
    asm("mov.b64 {%0, %1}, %2;" : "=f"(lo), "=f"(hi) : "l"(v));
}
__device__ __forceinline__ unsigned long long ffma2(unsigned long long a,
                                                    unsigned long long b,
                                                    unsigned long long c) {
    unsigned long long d;
    asm("fma.rn.f32x2 %0, %1, %2, %3;" : "=l"(d) : "l"(a), "l"(b), "l"(c));
    return d;
}
__device__ __forceinline__ unsigned long long fmul2(unsigned long long a,
                                                    unsigned long long b) {
    unsigned long long d;
    asm("mul.rn.f32x2 %0, %1, %2;" : "=l"(d) : "l"(a), "l"(b));
    return d;
}

// -------- Kwpv: Wpv = W2 @ Wv  [96,128], bpv = W2 @ bv ; also zero BN stats --------
__global__ void k_wpv(const float* __restrict__ W2, const float* __restrict__ Wv,
                      const float* __restrict__ bv) {
    __shared__ float w2s[CC];
    int p = blockIdx.x, c = threadIdx.x;
    if (p == 0) { g_csum[c] = 0.0; g_csumsq[c] = 0.0; }  // replay-safe reset
    w2s[c] = W2[p * CC + c];
    __syncthreads();
    float acc = 0.f;
#pragma unroll 4
    for (int i = 0; i < CC; i++) acc = fmaf(w2s[i], Wv[i * CC + c], acc);
    g_Wpv[p * CC + c] = acc;
    if (c == 0) {
        float a = 0.f;
        for (int i = 0; i < CC; i++) a = fmaf(w2s[i], bv[i], a);
        g_bpv[p] = a;
    }
}

// -------- K1: ConvTranspose (outer product x * Wt) + per-channel stats --------
__global__ __launch_bounds__(256) void k1_conv(const float* __restrict__ x,
                                               const float* __restrict__ Wt,
                                               const float* __restrict__ bt) {
    __shared__ float xs[BB * CC];
    __shared__ float red[16];
    int t = threadIdx.x;
    for (int i = t; i < BB * CC; i += 256) xs[i] = x[i];
    __syncthreads();
    int o = blockIdx.x;
    int l = (blockIdx.y << 8) + t;
    const float* wp = Wt + (size_t)o * LL + l;
    float acc[BB];
#pragma unroll
    for (int b = 0; b < BB; b++) acc[b] = 0.f;
#pragma unroll 4
    for (int i = 0; i < CC; i++) {
        float w = wp[(size_t)i * (CC * LL)];
#pragma unroll
        for (int b = 0; b < BB; b++) acc[b] = fmaf(xs[b * CC + i], w, acc[b]);
    }
    float bo = bt[o];
    float s1 = 0.f, s2 = 0.f;
#pragma unroll
    for (int b = 0; b < BB; b++) {
        float v = acc[b] + bo;
        g_hraw[((b * CC + o) << 12) + l] = v;
        s1 += v;
        s2 = fmaf(v, v, s2);
    }
#pragma unroll
    for (int off = 16; off; off >>= 1) {
        s1 += __shfl_xor_sync(0xffffffffu, s1, off);
        s2 += __shfl_xor_sync(0xffffffffu, s2, off);
    }
    int w = t >> 5, lane = t & 31;
    if (lane == 0) { red[w] = s1; red[8 + w] = s2; }
    __syncthreads();
    if (t == 0) {
        float a = 0.f, b2s = 0.f;
#pragma unroll
        for (int i = 0; i < 8; i++) { a += red[i]; b2s += red[8 + i]; }
        atomicAdd(&g_csum[o], (double)a);
        atomicAdd(&g_csumsq[o], (double)b2s);
    }
}

// -------- K3: per-block BN fold + BN+ReLU + {q,k,u} projections --------
__global__ __launch_bounds__(256) void k3_proj(const float* __restrict__ Wq,
                                               const float* __restrict__ bq,
                                               const float* __restrict__ Wk,
                                               const float* __restrict__ bk,
                                               const float* __restrict__ gamma,
                                               const float* __restrict__ beta) {
    __shared__ float hn[CC * 64];
    __shared__ float scs[CC];
    __shared__ float shs[CC];
    int t = threadIdx.x;
    if (t < CC) {
        double n = (double)(BB * LL);
        double m = g_csum[t] / n;
        double v = g_csumsq[t] / n - m * m;
        float sc = gamma[t] * rsqrtf((float)v + 1e-5f);
        scs[t] = sc;
        shs[t] = beta[t] - (float)m * sc;
    }
    __syncthreads();
    int b = blockIdx.y;
    int l0 = blockIdx.x * 64;
    for (int idx = t; idx < CC * 64; idx += 256) {
        int c = idx >> 6, j = idx & 63;
        float v = g_hraw[((b * CC + c) << 12) + l0 + j];
        v = fmaf(v, scs[c], shs[c]);
        hn[idx] = fmaxf(v, 0.f);
    }
    __syncthreads();
    int jg = t & 15, rg = t >> 4;
    int j0 = jg << 2, r0 = rg << 3;
    const float* Wbase;
    if (r0 < 16)      Wbase = Wq + r0 * CC;
    else if (r0 < 32) Wbase = Wk + (r0 - 16) * CC;
    else              Wbase = g_Wpv + (r0 - 32) * CC;
    float acc[8][4];
#pragma unroll
    for (int r = 0; r < 8; r++)
#pragma unroll
        for (int j = 0; j < 4; j++) acc[r][j] = 0.f;
#pragma unroll 2
    for (int c = 0; c < CC; c++) {
        float4 h4 = *reinterpret_cast<const float4*>(&hn[(c << 6) + j0]);
#pragma unroll
        for (int r = 0; r < 8; r++) {
            float w = __ldg(&Wbase[r * CC + c]);
            acc[r][0] = fmaf(w, h4.x, acc[r][0]);
            acc[r][1] = fmaf(w, h4.y, acc[r][1]);
            acc[r][2] = fmaf(w, h4.z, acc[r][2]);
            acc[r][3] = fmaf(w, h4.w, acc[r][3]);
        }
    }
    if (r0 < 16) {
#pragma unroll
        for (int r = 0; r < 8; r++) {
            float bias = bq[r0 + r];
#pragma unroll
            for (int j = 0; j < 4; j++)
                g_q[(((b << 12) + l0 + j0 + j) << 4) + r0 + r] = acc[r][j] + bias;
        }
    } else if (r0 < 32) {
#pragma unroll
        for (int r = 0; r < 8; r++) {
            float bias = bk[r0 - 16 + r];
#pragma unroll
            for (int j = 0; j < 4; j++)
                g_k[((b * DD + r0 - 16 + r) << 12) + l0 + j0 + j] = acc[r][j] + bias;
        }
    } else {
#pragma unroll
        for (int r = 0; r < 8; r++) {
            float bias = g_bpv[r0 - 32 + r];
#pragma unroll
            for (int j = 0; j < 4; j++)
                g_u[(((b << 12) + l0 + j0 + j) * PP) + r0 - 32 + r] = acc[r][j] + bias;
        }
    }
}

// -------- K4: flash attention with folded output projection --------
// s_s layout: row q (stride SSTR), column = m ^ ((qg&7)<<2), qg = q>>2.
// Swizzle spreads the 16 q-groups over 8 bank groups -> conflict-optimal reads.
__global__ __launch_bounds__(256, 2) void k4_attn(const float* __restrict__ b2,
                                                  float* __restrict__ y) {
    extern __shared__ float sm[];
    float* k_s  = sm;                        // [16][128]      2048 f
    float* u_s  = k_s + DD * TM;             // [128][96]     12288 f
    float* s_s  = u_s + TM * PP;             // [64][SSTR]     8704 f
    float* q_s  = s_s + TQ * SSTR;           // [16][QSTR]     1088 f
    float* rmax = q_s + DD * QSTR;           // [64]
    float* rsum = rmax + TQ;                 // [64]
    float* resc = rsum + TQ;                 // [64]

    int b = blockIdx.y;
    int l0 = blockIdx.x * TQ;
    int t = threadIdx.x;

    // stage q tile: global [B][L][16] -> smem [d][q]
    for (int idx = t; idx < TQ * DD; idx += 256) {
        int q = idx >> 4, d = idx & 15;
        q_s[d * QSTR + q] = g_q[(((b << 12) + l0 + q) << 4) + d];
    }
    if (t < TQ) { rmax[t] = -1e30f; rsum[t] = 0.f; }

    // score mapping: thread -> (4 queries, 8 keys)
    int mgS = t & 15, qgS = t >> 4;
    int m0 = mgS << 3, q0 = qgS << 2;
    int swW = (qgS & 7) << 2;

    // PV mapping: thread -> (4 queries, 6 p); warp = 2 pg x 16 qg (u broadcast)
    int pg = t >> 4, qgP = t & 15;
    int p0 = pg * 6, q0v = qgP << 2;
    int swR = (qgP & 7) << 2;

    unsigned long long acc2[12];
#pragma unroll
    for (int i = 0; i < 12; i++) acc2[i] = 0ull;

    const float4* kS4 = (const float4*)(g_k + ((size_t)b * DD << 12));

    for (int mt = 0; mt < LL; mt += TM) {
        __syncthreads();  // prior PV done with u_s / s_s

        // stage k tile [16][128]: 512 float4
        {
            int i = t;
#pragma unroll
            for (int r = 0; r < 2; r++, i += 256) {
                int d = i >> 5, j = i & 31;
                ((float4*)k_s)[(d << 5) + j] = kS4[(d << 10) + (mt >> 2) + j];
            }
        }
        // stage u tile [128][96]: contiguous 3072 float4
        {
            const float4* uS4 = (const float4*)(g_u + (size_t)((b << 12) + mt) * PP);
            float4* uD4 = (float4*)u_s;
#pragma unroll
            for (int r = 0; r < 12; r++) uD4[t + (r << 8)] = uS4[t + (r << 8)];
        }
        __syncthreads();

        // ---- scores: S[4q][8m] via packed f32x2 FMA ----
        unsigned long long sa[16];
#pragma unroll
        for (int i = 0; i < 16; i++) sa[i] = 0ull;
#pragma unroll
        for (int d = 0; d < DD; d++) {
            float4 q4 = *reinterpret_cast<const float4*>(&q_s[d * QSTR + q0]);
            ulonglong2 ka = *reinterpret_cast<const ulonglong2*>(&k_s[d * TM + m0]);
            ulonglong2 kb = *reinterpret_cast<const ulonglong2*>(&k_s[d * TM + m0 + 4]);
            float qv[4] = {q4.x, q4.y, q4.z, q4.w};
#pragma unroll
            for (int i = 0; i < 4; i++) {
                unsigned long long qp = pk2(qv[i], qv[i]);
                sa[i * 4 + 0] = ffma2(qp, ka.x, sa[i * 4 + 0]);
                sa[i * 4 + 1] = ffma2(qp, ka.y, sa[i * 4 + 1]);
                sa[i * 4 + 2] = ffma2(qp, kb.x, sa[i * 4 + 2]);
                sa[i * 4 + 3] = ffma2(qp, kb.y, sa[i * 4 + 3]);
            }
        }
        float lm[4];
#pragma unroll
        for (int i = 0; i < 4; i++) {
            float mx = -1e30f;
#pragma unroll
            for (int j = 0; j < 4; j++) {
                float a, bb;
                upk2(sa[i * 4 + j], a, bb);
                mx = fmaxf(mx, fmaxf(a, bb));
            }
            lm[i] = mx;
        }
#pragma unroll
        for (int off = 8; off; off >>= 1)
#pragma unroll
            for (int i = 0; i < 4; i++)
                lm[i] = fmaxf(lm[i], __shfl_xor_sync(0xffffffffu, lm[i], off));

        float nm[4], ps[4];
#pragma unroll
        for (int i = 0; i < 4; i++) nm[i] = fmaxf(rmax[q0 + i], lm[i]);
#pragma unroll
        for (int i = 0; i < 4; i++) {
            float a, bb, acc = 0.f;
            float* srow = &s_s[(q0 + i) * SSTR];
#pragma unroll
            for (int j = 0; j < 4; j++) {
                upk2(sa[i * 4 + j], a, bb);
                float ea = __expf(a - nm[i]);
                float eb = __expf(bb - nm[i]);
                *reinterpret_cast<float2*>(&srow[(m0 + 2 * j) ^ swW]) = make_float2(ea, eb);
                acc += ea + eb;
            }
            ps[i] = acc;
        }
#pragma unroll
        for (int off = 8; off; off >>= 1)
#pragma unroll
            for (int i = 0; i < 4; i++)
                ps[i] += __shfl_xor_sync(0xffffffffu, ps[i], off);
        if (mgS == 0) {
#pragma unroll
            for (int i = 0; i < 4; i++) {
                int q = q0 + i;
                float om = rmax[q];
                float r = __expf(om - nm[i]);
                resc[q] = r;
                rsum[q] = rsum[q] * r + ps[i];
                rmax[q] = nm[i];
            }
        }
        __syncthreads();

        // ---- PV: acc[q][p] = acc*rescale + sum_m e[q][m] * u[m][p] ----
#pragma unroll
        for (int qi = 0; qi < 4; qi++) {
            float r = resc[q0v + qi];
            unsigned long long rp = pk2(r, r);
            acc2[qi * 3 + 0] = fmul2(acc2[qi * 3 + 0], rp);
            acc2[qi * 3 + 1] = fmul2(acc2[qi * 3 + 1], rp);
            acc2[qi * 3 + 2] = fmul2(acc2[qi * 3 + 2], rp);
        }
        for (int mc = 0; mc < TM; mc += 4) {
            float4 s4[4];
#pragma unroll
            for (int qi = 0; qi < 4; qi++)
                s4[qi] = *reinterpret_cast<const float4*>(
                    &s_s[(q0v + qi) * SSTR + (mc ^ swR)]);
#pragma unroll
            for (int mm = 0; mm < 4; mm++) {
                const float* up = u_s + (mc + mm) * PP + p0;
                unsigned long long u0 = *reinterpret_cast<const unsigned long long*>(up);
                unsigned long long u1 = *reinterpret_cast<const unsigned long long*>(up + 2);
                unsigned long long u2 = *reinterpret_cast<const unsigned long long*>(up + 4);
#pragma unroll
                for (int qi = 0; qi < 4; qi++) {
                    float sv = reinterpret_cast<const float*>(&s4[qi])[mm];
                    unsigned long long sp = pk2(sv, sv);
                    acc2[qi * 3 + 0] = ffma2(sp, u0, acc2[qi * 3 + 0]);
                    acc2[qi * 3 + 1] = ffma2(sp, u1, acc2[qi * 3 + 1]);
                    acc2[qi * 3 + 2] = ffma2(sp, u2, acc2[qi * 3 + 2]);
                }
            }
        }
    }

    // epilogue: y[b,p,l] = acc/rsum + b2[p]
#pragma unroll
    for (int qi = 0; qi < 4; qi++) {
        float inv = 1.0f / rsum[q0v + qi];
        int l = l0 + q0v + qi;
#pragma unroll
        for (int k = 0; k < 3; k++) {
            float lo, hi;
            upk2(acc2[qi * 3 + k], lo, hi);
            int p = p0 + 2 * k;
            y[((b * PP + p) << 12) + l]     = fmaf(lo, inv, b2[p]);
            y[((b * PP + p + 1) << 12) + l] = fmaf(hi, inv, b2[p + 1]);
        }
    }
}

extern "C" void kernel_launch(void* const* d_in, const int* in_sizes, int n_in,
                              void* d_out, int out_size) {
    const float* x     = (const float*)d_in[0];
    const float* Wt    = (const float*)d_in[1];
    const float* bt    = (const float*)d_in[2];
    const float* gamma = (const float*)d_in[3];
    const float* beta  = (const float*)d_in[4];
    const float* Wq    = (const float*)d_in[5];
    const float* bq    = (const float*)d_in[6];
    const float* Wk    = (const float*)d_in[7];
    const float* bk    = (const float*)d_in[8];
    const float* Wv    = (const float*)d_in[9];
    const float* bv    = (const float*)d_in[10];
    const float* W2    = (const float*)d_in[11];
    const float* b2    = (const float*)d_in[12];
    float* y = (float*)d_out;

    const int attn_smem = (DD * TM + TM * PP + TQ * SSTR + DD * QSTR + 3 * TQ) * 4;
    cudaFuncSetAttribute(k4_attn, cudaFuncAttributeMaxDynamicSharedMemorySize, attn_smem);

    k_wpv<<<PP, 128>>>(W2, Wv, bv);
    k1_conv<<<dim3(CC, LL / 256), 256>>>(x, Wt, bt);
    k3_proj<<<dim3(LL / 64, BB), 256>>>(Wq, bq, Wk, bk, gamma, beta);
    k4_attn<<<dim3(LL / TQ, BB), 256, attn_smem>>>(b2, y);
}